// round 9
// baseline (speedup 1.0000x reference)
#include <cuda_runtime.h>
#include <math.h>
#include <stdint.h>

typedef unsigned long long ull;

#define Bv 2
#define Nv 10000
#define Ev 160000
#define Hv 128
#define ETv 8
#define BN (Bv*Nv)
#define EPSv 1e-5f
#define RSQRT_H 0.08838834764831843f

#define APAD 130
#define CPAD 132
#define SMEM_GEMM (2*128*APAD*4)   // 133120 bytes

// ---------------- scratch ----------------
__device__ float g_Q[BN*Hv];
__device__ float g_K[BN*Hv];
__device__ float g_V[BN*Hv];
__device__ float g_Agg[BN*Hv];
__device__ float g_Hmid[BN*Hv];
__device__ float g_segsum[BN];
__device__ float g_Ke[ETv*Hv];
__device__ float g_Ve[ETv*Hv];
__device__ float g_eL[ETv];

// ---------------- helpers ----------------
__device__ __forceinline__ void red_add_v4(float* p, float4 v) {
    asm volatile("red.global.add.v4.f32 [%0], {%1,%2,%3,%4};"
                 :: "l"(p), "f"(v.x), "f"(v.y), "f"(v.z), "f"(v.w) : "memory");
}
__device__ __forceinline__ void split_tf32(float x, unsigned& hi, unsigned& lo) {
    asm("cvt.rna.tf32.f32 %0, %1;" : "=r"(hi) : "f"(x));
    float l = x - __uint_as_float(hi);
    asm("cvt.rna.tf32.f32 %0, %1;" : "=r"(lo) : "f"(l));
}
__device__ __forceinline__ void mma_tf32(float* c, const unsigned* a, const unsigned* b) {
    asm volatile("mma.sync.aligned.m16n8k8.row.col.f32.tf32.tf32.f32 "
        "{%0,%1,%2,%3}, {%4,%5,%6,%7}, {%8,%9}, {%0,%1,%2,%3};"
        : "+f"(c[0]), "+f"(c[1]), "+f"(c[2]), "+f"(c[3])
        : "r"(a[0]), "r"(a[1]), "r"(a[2]), "r"(a[3]), "r"(b[0]), "r"(b[1]));
}

// ---------------- 0: zero scratch ----------------
__global__ void zero_init() {
    int i = blockIdx.x * blockDim.x + threadIdx.x;
    int stride = gridDim.x * blockDim.x;
    for (int j = i; j < BN*Hv; j += stride) g_Agg[j] = 0.0f;
    for (int j = i; j < BN; j += stride) g_segsum[j] = 0.0f;
}

// ---------------- 1: edge-type projections ----------------
__global__ void prep_edge(const float* __restrict__ eemb,
                          const float* __restrict__ Wk,
                          const float* __restrict__ Wv,
                          const float* __restrict__ We,
                          const float* __restrict__ be) {
    int t = threadIdx.x >> 7;
    int j = threadIdx.x & 127;
    float ake = 0.f, ave = 0.f;
    #pragma unroll 4
    for (int k = 0; k < Hv; k++) {
        float e = eemb[t*Hv + k];
        ake += e * Wk[k*Hv + j];
        ave += e * Wv[k*Hv + j];
    }
    g_Ke[t*Hv + j] = ake;
    g_Ve[t*Hv + j] = ave;
    if (j == 0) {
        float s = 0.f;
        for (int k = 0; k < Hv; k++) s += eemb[t*Hv + k] * We[k];
        g_eL[t] = s + be[0];
    }
}

// ================= tf32 mma GEMM framework =================
// CTA tile 128x128, 256 threads = 8 warps; warp tile 32x64.
// warp_m = (wid&3)*32, warp_n = (wid>>2)*64.
// As[row][k] stride APAD; Bs[n][k] = W[k][n] stride APAD.

__device__ __forceinline__ void stage_As(float* As, int tid, int row0,
                                         const float* __restrict__ s0,
                                         const float* __restrict__ s1,
                                         bool use_inv) {
    #pragma unroll
    for (int i = 0; i < 16; i++) {
        int e = tid + i * 256;
        int r = e >> 5, kk = (e & 31) * 4;
        int row = row0 + r;
        float4 a = make_float4(0.f, 0.f, 0.f, 0.f);
        if (row < BN) {
            a = *(const float4*)&s0[row * Hv + kk];
            if (s1) {
                float4 b = *(const float4*)&s1[row * Hv + kk];
                a.x += b.x; a.y += b.y; a.z += b.z; a.w += b.w;
            }
            if (use_inv) {
                float ssum = g_segsum[row];
                float inv = (ssum > 0.f) ? 1.f / ssum : 0.f;
                a.x *= inv; a.y *= inv; a.z *= inv; a.w *= inv;
            }
        }
        *(float2*)&As[r * APAD + kk]     = make_float2(a.x, a.y);
        *(float2*)&As[r * APAD + kk + 2] = make_float2(a.z, a.w);
    }
}

__device__ __forceinline__ void stage_Bs(float* Bs, int tid,
                                         const float* __restrict__ W) {
    #pragma unroll
    for (int i = 0; i < 64; i++) {
        int e = tid + i * 256;
        int k = e >> 7, n = e & 127;
        Bs[n * APAD + k] = W[k * Hv + n];
    }
}

// 3xTF32 inner product over K=128 into c[2][8][4]
__device__ __forceinline__ void mma_loop(const float* As, const float* Bs,
                                         int warp_m, int warp_n, int lane,
                                         float c[2][8][4]) {
    int lr = lane >> 2;          // 0..7
    int lc = lane & 3;           // 0..3
    #pragma unroll
    for (int ks = 0; ks < 16; ks++) {
        int k0 = ks * 8;
        unsigned ahi[2][4], alo[2][4];
        #pragma unroll
        for (int mi = 0; mi < 2; mi++) {
            int r0 = warp_m + mi * 16 + lr;
            float a0 = As[r0 * APAD + k0 + lc];
            float a1 = As[(r0 + 8) * APAD + k0 + lc];
            float a2 = As[r0 * APAD + k0 + lc + 4];
            float a3 = As[(r0 + 8) * APAD + k0 + lc + 4];
            split_tf32(a0, ahi[mi][0], alo[mi][0]);
            split_tf32(a1, ahi[mi][1], alo[mi][1]);
            split_tf32(a2, ahi[mi][2], alo[mi][2]);
            split_tf32(a3, ahi[mi][3], alo[mi][3]);
        }
        unsigned bhi[8][2], blo[8][2];
        #pragma unroll
        for (int ni = 0; ni < 8; ni++) {
            int n = warp_n + ni * 8 + lr;
            float b0 = Bs[n * APAD + k0 + lc];
            float b1 = Bs[n * APAD + k0 + lc + 4];
            split_tf32(b0, bhi[ni][0], blo[ni][0]);
            split_tf32(b1, bhi[ni][1], blo[ni][1]);
        }
        #pragma unroll
        for (int mi = 0; mi < 2; mi++)
            #pragma unroll
            for (int ni = 0; ni < 8; ni++) {
                mma_tf32(c[mi][ni], ahi[mi], bhi[ni]);
                mma_tf32(c[mi][ni], ahi[mi], blo[ni]);
                mma_tf32(c[mi][ni], alo[mi], bhi[ni]);
            }
    }
}

// write C frags into Cs[128][CPAD]
__device__ __forceinline__ void store_C(float* Cs, int warp_m, int warp_n,
                                        int lane, float c[2][8][4]) {
    int lr = lane >> 2, lc = lane & 3;
    #pragma unroll
    for (int mi = 0; mi < 2; mi++)
        #pragma unroll
        for (int ni = 0; ni < 8; ni++) {
            int row = warp_m + mi * 16 + lr;
            int col = warp_n + ni * 8 + 2 * lc;
            Cs[row * CPAD + col]           = c[mi][ni][0];
            Cs[row * CPAD + col + 1]       = c[mi][ni][1];
            Cs[(row + 8) * CPAD + col]     = c[mi][ni][2];
            Cs[(row + 8) * CPAD + col + 1] = c[mi][ni][3];
        }
}

// ---------------- 2: QKV GEMM (z selects Q/K/V) ----------------
__global__ void __launch_bounds__(256, 1)
gemm_qkv(const float* __restrict__ hidden, const float* __restrict__ temb,
         const float* __restrict__ Wq, const float* __restrict__ bq,
         const float* __restrict__ Wk, const float* __restrict__ bk,
         const float* __restrict__ Wv, const float* __restrict__ bv)
{
    extern __shared__ float sm[];
    float* As = sm;
    float* Bs = sm + 128 * APAD;
    float* Cs = sm;                       // reused after compute
    int tid = threadIdx.x, wid = tid >> 5, lane = tid & 31;
    int warp_m = (wid & 3) * 32, warp_n = (wid >> 2) * 64;
    int row0 = blockIdx.x * 128;
    int which = blockIdx.z;
    const float* W    = which == 0 ? Wq : (which == 1 ? Wk : Wv);
    const float* bias = which == 0 ? bq : (which == 1 ? bk : bv);
    float* out        = which == 0 ? g_Q : (which == 1 ? g_K : g_V);
    const float* s1   = (which < 2) ? temb : nullptr;

    stage_As(As, tid, row0, hidden, s1, false);
    stage_Bs(Bs, tid, W);
    __syncthreads();

    float c[2][8][4];
    #pragma unroll
    for (int mi = 0; mi < 2; mi++)
        #pragma unroll
        for (int ni = 0; ni < 8; ni++)
            #pragma unroll
            for (int j = 0; j < 4; j++) c[mi][ni][j] = 0.f;
    mma_loop(As, Bs, warp_m, warp_n, lane, c);
    __syncthreads();
    store_C(Cs, warp_m, warp_n, lane, c);
    __syncthreads();

    #pragma unroll
    for (int i = 0; i < 16; i++) {
        int e = tid + i * 256;
        int r = e >> 5, c4 = (e & 31) * 4;
        int row = row0 + r;
        if (row < BN) {
            float4 v = *(float4*)&Cs[r * CPAD + c4];
            v.x += __ldg(&bias[c4+0]); v.y += __ldg(&bias[c4+1]);
            v.z += __ldg(&bias[c4+2]); v.w += __ldg(&bias[c4+3]);
            *(float4*)&out[row * Hv + c4] = v;
        }
    }
}

// ---------------- 3: FUSED edge kernel ----------------
__global__ void edge_fused(const int* __restrict__ eidx, const int* __restrict__ etype)
{
    int w = (blockIdx.x * blockDim.x + threadIdx.x) >> 5;
    int lane = threadIdx.x & 31;
    if (w >= Ev) return;
    int src = eidx[w];
    int tgt = eidx[Ev + w];
    int ty  = etype[w];
    float4 ke = *(const float4*)&g_Ke[ty*Hv + lane*4];
    float4 ve = *(const float4*)&g_Ve[ty*Hv + lane*4];
    float el = g_eL[ty];

    float4 q0 = *(const float4*)&g_Q[(0*Nv + tgt)*Hv + lane*4];
    float4 k0 = *(const float4*)&g_K[(0*Nv + src)*Hv + lane*4];
    float4 q1 = *(const float4*)&g_Q[(1*Nv + tgt)*Hv + lane*4];
    float4 k1 = *(const float4*)&g_K[(1*Nv + src)*Hv + lane*4];

    float s0 = q0.x*(k0.x+ke.x) + q0.y*(k0.y+ke.y) + q0.z*(k0.z+ke.z) + q0.w*(k0.w+ke.w);
    float s1 = q1.x*(k1.x+ke.x) + q1.y*(k1.y+ke.y) + q1.z*(k1.z+ke.z) + q1.w*(k1.w+ke.w);
    #pragma unroll
    for (int off = 16; off > 0; off >>= 1) {
        s0 += __shfl_xor_sync(0xffffffffu, s0, off);
        s1 += __shfl_xor_sync(0xffffffffu, s1, off);
    }
    float ex0 = expf(s0 * RSQRT_H + el);
    float ex1 = expf(s1 * RSQRT_H + el);
    if (lane == 0) {
        atomicAdd(&g_segsum[tgt], ex0);
        atomicAdd(&g_segsum[Nv + tgt], ex1);
    }
    float4 v0 = *(const float4*)&g_V[(0*Nv + src)*Hv + lane*4];
    float4 v1 = *(const float4*)&g_V[(1*Nv + src)*Hv + lane*4];
    float4 a0 = make_float4(ex0*(v0.x+ve.x), ex0*(v0.y+ve.y),
                            ex0*(v0.z+ve.z), ex0*(v0.w+ve.w));
    float4 a1 = make_float4(ex1*(v1.x+ve.x), ex1*(v1.y+ve.y),
                            ex1*(v1.z+ve.z), ex1*(v1.w+ve.w));
    red_add_v4(&g_Agg[(0*Nv + tgt)*Hv + lane*4], a0);
    red_add_v4(&g_Agg[(1*Nv + tgt)*Hv + lane*4], a1);
}

// ---------------- 4: MLP GEMM1 (3 K-chunks, SiLU) ----------------
__global__ void __launch_bounds__(256, 1)
gemm_mlp1(const float* __restrict__ hidden, const float* __restrict__ temb,
          const float* __restrict__ W1, const float* __restrict__ b1)
{
    extern __shared__ float sm[];
    float* As = sm;
    float* Bs = sm + 128 * APAD;
    float* Cs = sm;
    int tid = threadIdx.x, wid = tid >> 5, lane = tid & 31;
    int warp_m = (wid & 3) * 32, warp_n = (wid >> 2) * 64;
    int row0 = blockIdx.x * 128;

    float c[2][8][4];
    #pragma unroll
    for (int mi = 0; mi < 2; mi++)
        #pragma unroll
        for (int ni = 0; ni < 8; ni++)
            #pragma unroll
            for (int j = 0; j < 4; j++) c[mi][ni][j] = 0.f;

    for (int c3 = 0; c3 < 3; c3++) {
        const float* s0 = (c3 == 0) ? hidden : (c3 == 1 ? g_Agg : temb);
        stage_As(As, tid, row0, s0, nullptr, c3 == 1);
        stage_Bs(Bs, tid, W1 + c3 * 128 * Hv);
        __syncthreads();
        mma_loop(As, Bs, warp_m, warp_n, lane, c);
        __syncthreads();
    }
    store_C(Cs, warp_m, warp_n, lane, c);
    __syncthreads();

    #pragma unroll
    for (int i = 0; i < 16; i++) {
        int e = tid + i * 256;
        int r = e >> 5, c4 = (e & 31) * 4;
        int row = row0 + r;
        if (row < BN) {
            float4 v = *(float4*)&Cs[r * CPAD + c4];
            v.x += __ldg(&b1[c4+0]); v.y += __ldg(&b1[c4+1]);
            v.z += __ldg(&b1[c4+2]); v.w += __ldg(&b1[c4+3]);
            v.x = v.x / (1.f + expf(-v.x));
            v.y = v.y / (1.f + expf(-v.y));
            v.z = v.z / (1.f + expf(-v.z));
            v.w = v.w / (1.f + expf(-v.w));
            *(float4*)&g_Hmid[row * Hv + c4] = v;
        }
    }
}

// ---------------- 5: GEMM2 + residual + LayerNorm ----------------
__global__ void __launch_bounds__(256, 1)
gemm2_ln(const float* __restrict__ hidden,
         const float* __restrict__ W2, const float* __restrict__ b2,
         const float* __restrict__ gamma, const float* __restrict__ beta,
         float* __restrict__ out)
{
    extern __shared__ float sm[];
    float* As = sm;
    float* Bs = sm + 128 * APAD;
    float* Cs = sm;
    float* s_mean = sm + 128 * CPAD;
    float* s_rstd = s_mean + 128;
    int tid = threadIdx.x, wid = tid >> 5, lane = tid & 31;
    int warp_m = (wid & 3) * 32, warp_n = (wid >> 2) * 64;
    int row0 = blockIdx.x * 128;

    stage_As(As, tid, row0, g_Hmid, nullptr, false);
    stage_Bs(Bs, tid, W2);
    __syncthreads();

    float c[2][8][4];
    #pragma unroll
    for (int mi = 0; mi < 2; mi++)
        #pragma unroll
        for (int ni = 0; ni < 8; ni++)
            #pragma unroll
            for (int j = 0; j < 4; j++) c[mi][ni][j] = 0.f;
    mma_loop(As, Bs, warp_m, warp_n, lane, c);
    __syncthreads();
    store_C(Cs, warp_m, warp_n, lane, c);
    __syncthreads();

    // pass 1: += bias + residual
    #pragma unroll
    for (int i = 0; i < 16; i++) {
        int e = tid + i * 256;
        int r = e >> 5, c4 = (e & 31) * 4;
        int row = row0 + r;
        if (row < BN) {
            float4 h = *(const float4*)&hidden[row * Hv + c4];
            float4 v = *(float4*)&Cs[r * CPAD + c4];
            v.x += h.x + __ldg(&b2[c4+0]);
            v.y += h.y + __ldg(&b2[c4+1]);
            v.z += h.z + __ldg(&b2[c4+2]);
            v.w += h.w + __ldg(&b2[c4+3]);
            *(float4*)&Cs[r * CPAD + c4] = v;
        }
    }
    __syncthreads();
    // pass 2: per-row stats
    if (tid < 128) {
        float s = 0.f, ss = 0.f;
        #pragma unroll 8
        for (int c4 = 0; c4 < 128; c4 += 4) {
            float4 v = *(float4*)&Cs[tid * CPAD + c4];
            s  += v.x + v.y + v.z + v.w;
            ss += v.x*v.x + v.y*v.y + v.z*v.z + v.w*v.w;
        }
        float mean = s * (1.f / 128.f);
        float var  = ss * (1.f / 128.f) - mean * mean;
        s_mean[tid] = mean;
        s_rstd[tid] = rsqrtf(var + EPSv);
    }
    __syncthreads();
    // pass 3: normalize & write
    #pragma unroll
    for (int i = 0; i < 16; i++) {
        int e = tid + i * 256;
        int r = e >> 5, c4 = (e & 31) * 4;
        int row = row0 + r;
        if (row < BN) {
            float m = s_mean[r], rstd = s_rstd[r];
            float4 v = *(float4*)&Cs[r * CPAD + c4];
            float4 o;
            o.x = (v.x - m) * rstd * __ldg(&gamma[c4+0]) + __ldg(&beta[c4+0]);
            o.y = (v.y - m) * rstd * __ldg(&gamma[c4+1]) + __ldg(&beta[c4+1]);
            o.z = (v.z - m) * rstd * __ldg(&gamma[c4+2]) + __ldg(&beta[c4+2]);
            o.w = (v.w - m) * rstd * __ldg(&gamma[c4+3]) + __ldg(&beta[c4+3]);
            *(float4*)&out[row * Hv + c4] = o;
        }
    }
}

// ---------------- launch ----------------
extern "C" void kernel_launch(void* const* d_in, const int* in_sizes, int n_in,
                              void* d_out, int out_size)
{
    const float* hidden = (const float*)d_in[0];
    const float* temb   = (const float*)d_in[1];
    const int*   eidx   = (const int*)d_in[2];
    const int*   etype  = (const int*)d_in[3];
    const float* eemb   = (const float*)d_in[4];
    const float* Wq = (const float*)d_in[5];  const float* bq = (const float*)d_in[6];
    const float* Wk = (const float*)d_in[7];  const float* bk = (const float*)d_in[8];
    const float* Wv = (const float*)d_in[9];  const float* bv = (const float*)d_in[10];
    const float* We = (const float*)d_in[11]; const float* be = (const float*)d_in[12];
    const float* W1 = (const float*)d_in[13]; const float* b1 = (const float*)d_in[14];
    const float* W2 = (const float*)d_in[15]; const float* b2 = (const float*)d_in[16];
    const float* gamma = (const float*)d_in[17]; const float* beta = (const float*)d_in[18];
    float* out = (float*)d_out;

    cudaFuncSetAttribute(gemm_qkv,  cudaFuncAttributeMaxDynamicSharedMemorySize, SMEM_GEMM);
    cudaFuncSetAttribute(gemm_mlp1, cudaFuncAttributeMaxDynamicSharedMemorySize, SMEM_GEMM);
    cudaFuncSetAttribute(gemm2_ln,  cudaFuncAttributeMaxDynamicSharedMemorySize, SMEM_GEMM);

    int gb = (BN + 127) / 128;   // 157
    zero_init<<<2560, 256>>>();
    prep_edge<<<1, 1024>>>(eemb, Wk, Wv, We, be);
    dim3 gq(gb, 1, 3);
    gemm_qkv<<<gq, 256, SMEM_GEMM>>>(hidden, temb, Wq, bq, Wk, bk, Wv, bv);
    edge_fused<<<Ev/8, 256>>>(eidx, etype);
    gemm_mlp1<<<gb, 256, SMEM_GEMM>>>(hidden, temb, W1, b1);
    gemm2_ln<<<gb, 256, SMEM_GEMM>>>(hidden, W2, b2, gamma, beta, out);
}